// round 14
// baseline (speedup 1.0000x reference)
#include <cuda_runtime.h>
#include <math.h>

#define NB 4
#define T 72000
#define TS 300
#define NCB 8
#define CBS 1024
#define CBD 64
#define DM 512

// out offsets (floats): a_tokens, b_logits, s1, s2, s3, s4
#define OFF_A  0
#define OFF_BL 9600
#define OFF_S1 316800
#define OFF_S2 316824
#define OFF_S3 317848
#define OFF_S4 319896

#define NPOS (NB * TS)   // 1200
#define N_A2 (NPOS * 7 * 128)
#define N_A3 (NPOS * 3 * 256)

__device__ float g_cn[NCB * CBS];         // 0.5*|c|^2
__device__ float g_w2t[320 * 128];        // [(kk*64+i)][o]
__device__ float g_w3t[640 * 256];        // [(kk*128+i)][o]
__device__ float g_w4t[768 * 512];        // [(kk*256+i)][o]
__device__ float g_hwt[DM * 256];         // [d][h*64+o]
__device__ float g_cbt[NCB * CBD * CBS];  // [i][d][code]
__device__ float g_a1[NPOS * 11 * 64];    // elu(conv1) [pos][off 0..10][ch]
__device__ float g_a2part[2][N_A2];       // conv2 K-split partials (raw)
__device__ float g_a2[N_A2];              // elu(conv2) combined
__device__ float g_a3part[2][N_A3];       // conv3 K-split partials (raw)
__device__ float g_a3[N_A3];              // elu(conv3) combined
__device__ float g_zpart[2][NPOS * DM];   // conv4 K-split partials (raw)

__device__ __forceinline__ float elu1(float x) { return x > 0.f ? x : expm1f(x); }

__device__ __forceinline__ unsigned fordu(float f) {
    unsigned u = __float_as_uint(f);
    return u ^ (unsigned)(((int)u >> 31) | 0x80000000);
}

// packed f32x2 helpers (rvq dot phase)
__device__ __forceinline__ unsigned long long pack2(float lo, float hi) {
    unsigned long long r;
    asm("mov.b64 %0, {%1, %2};" : "=l"(r) : "f"(lo), "f"(hi));
    return r;
}
__device__ __forceinline__ void fma2(unsigned long long& d,
                                     unsigned long long a, unsigned long long b) {
    asm("fma.rn.f32x2 %0, %1, %2, %0;" : "+l"(d) : "l"(a), "l"(b));
}
__device__ __forceinline__ float lo32(unsigned long long v) {
    return __uint_as_float((unsigned)v);
}
__device__ __forceinline__ float hi32(unsigned long long v) {
    return __uint_as_float((unsigned)(v >> 32));
}

// ---------------------------------------------------------------------------
// prep + conv1 merged. blocks [0,1224): transposes, [1224,1480): code norms,
// [1480,1630): conv1 (150 blocks x 8 positions).
// ---------------------------------------------------------------------------
__global__ __launch_bounds__(256) void prep_conv1_kernel(
    const float* __restrict__ w2, const float* __restrict__ w3,
    const float* __restrict__ w4, const float* __restrict__ hw,
    const float* __restrict__ cb,
    const float* __restrict__ audio,
    const float* __restrict__ w1c, const float* __restrict__ b1c,
    float* __restrict__ out)
{
    __shared__ float ts[32 * 33];
    __shared__ float aud[8 * 17];
    __shared__ float w1s[64 * 7];
    const int tid = threadIdx.x;
    int bid = blockIdx.x;

    if (bid < 1224) {
        const float* src; float* dst;
        int r0, c0, SP, NO, cdiv, cmul, cin, dbase = 0;
        if (bid < 40) {                // w2: src 128x320 -> dst[(kk*64+i)][o]
            src = w2; dst = g_w2t; SP = 320; NO = 128; cdiv = 5; cmul = 64; cin = 1;
            r0 = (bid & 3) * 32; c0 = (bid >> 2) * 32;
        } else if (bid < 200) {        // w3: 256x640
            bid -= 40;
            src = w3; dst = g_w3t; SP = 640; NO = 256; cdiv = 5; cmul = 128; cin = 1;
            r0 = (bid & 7) * 32; c0 = (bid >> 3) * 32;
        } else if (bid < 584) {        // w4: 512x768
            bid -= 200;
            src = w4; dst = g_w4t; SP = 768; NO = 512; cdiv = 3; cmul = 256; cin = 1;
            r0 = (bid & 15) * 32; c0 = (bid >> 4) * 32;
        } else if (bid < 712) {        // hw: 256x512 plain transpose
            bid -= 584;
            src = hw; dst = g_hwt; SP = 512; NO = 256; cdiv = 1; cmul = 1; cin = 0;
            r0 = (bid & 7) * 32; c0 = (bid >> 3) * 32;
        } else {                       // cb: per-codebook 1024x64 plain transpose
            bid -= 712;
            int i = bid >> 6; int t = bid & 63;
            src = cb + i * 65536; dst = g_cbt; dbase = i * 65536;
            SP = 64; NO = 1024; cdiv = 1; cmul = 1; cin = 0;
            r0 = (t >> 1) * 32; c0 = (t & 1) * 32;
        }
        for (int l = tid; l < 1024; l += 256) {
            int r = l >> 5, c = l & 31;
            ts[r * 33 + c] = src[(r0 + r) * SP + c0 + c];
        }
        __syncthreads();
        for (int l = tid; l < 1024; l += 256) {
            int r = l >> 5, c = l & 31;
            int colidx = c0 + r;
            int drow;
            if (cin) drow = (colidx % cdiv) * cmul + colidx / cdiv;
            else     drow = colidx;
            dst[dbase + drow * NO + r0 + c] = ts[c * 33 + r];
        }
    } else if (bid < 1480) {
        bid -= 1224;
        const int wid = tid >> 5, lane = tid & 31;
        int code0 = bid * 32 + wid * 4;
        #pragma unroll
        for (int cc = 0; cc < 4; cc++) {
            const float* p = cb + (code0 + cc) * CBD;
            float v1 = p[lane], v2 = p[lane + 32];
            float s = fmaf(v1, v1, v2 * v2);
            #pragma unroll
            for (int off = 16; off > 0; off >>= 1)
                s += __shfl_down_sync(0xFFFFFFFFu, s, off);
            if (lane == 0) g_cn[code0 + cc] = 0.5f * s;
        }
    } else {
        // conv1: 8 positions per block
        bid -= 1480;
        const int pos0 = bid * 8;
        for (int idx = tid; idx < 64 * 7; idx += 256) w1s[idx] = w1c[idx];
        for (int idx = tid; idx < 8 * 17; idx += 256) {
            int p = idx / 17, u = idx - p * 17;
            int pos = pos0 + p;
            int b = pos / TS, t = pos - b * TS;
            aud[idx] = audio[b * T + t * 240 + 223 + u];
        }
        __syncthreads();
        for (int idx = tid; idx < 8 * 11 * 64; idx += 256) {
            int ch = idx & 63;
            int r = idx >> 6;
            int j = r % 11, p = r / 11;
            float acc = b1c[ch];
            #pragma unroll
            for (int k = 0; k < 7; k++) acc = fmaf(w1s[ch * 7 + k], aud[p * 17 + j + k], acc);
            g_a1[(pos0 + p) * 704 + j * 64 + ch] = elu1(acc);
        }
        if (bid == 0 && tid < 24) {
            int b = tid / 6, u = tid % 6;
            out[OFF_S1 + tid] = audio[b * T + (T - 6) + u];
        }
    }
}

// ---------------------------------------------------------------------------
// smem-smem GEMM conv: BM=64, BN=64, BK=16, 256 thr, 4x4 reg tile,
// double-buffered smem + register-pipelined LDS.
// EPI=1: dst = elu(acc + bias). EPI=0: dst = raw acc (partial).
// NSPL: K-splits on blockIdx.y (y = spl*(NOUT/64) + ntile).
// ---------------------------------------------------------------------------
#define GP 68
template<int KDIM, int NOUT, int MROWS, int JDIV, int JMUL, int CH, int EPI, int NSPL>
__global__ __launch_bounds__(256) void gemm_conv(
    const float* __restrict__ src, const float* __restrict__ wt,
    const float* __restrict__ bias, float* __restrict__ dst)
{
    __shared__ float As[2][16 * GP];
    __shared__ float Bs[2][16 * GP];

    const int tid = threadIdx.x;
    const int tx = tid & 15;
    const int ty = tid >> 4;
    const int m0 = blockIdx.x * 64;
    int yb = blockIdx.y;
    if (NSPL > 1) {
        int spl = yb / (NOUT / 64);
        yb -= spl * (NOUT / 64);
        src += spl * KDIM;            // additive k-origin (k contiguous per row window)
        wt  += spl * KDIM * NOUT;
        dst += spl * MROWS * NOUT;
    }
    const int n0 = yb * 64;

    const int m_l = tid & 63;
    const int k4 = tid >> 6;
    int mrow = m0 + m_l; if (mrow >= MROWS) mrow = MROWS - 1;   // clamp (stores guarded)
    const float* spA = src + (mrow / JDIV) * JMUL + (mrow % JDIV) * CH;

    const int k_l = tid >> 4;
    const int n4 = tid & 15;
    const float* spB = wt + k_l * NOUT + n0 + n4 * 4;

    float acc[4][4];
    #pragma unroll
    for (int i = 0; i < 4; i++)
        #pragma unroll
        for (int j = 0; j < 4; j++) acc[i][j] = 0.f;

    float4 av = *(const float4*)(spA + k4 * 4);
    float4 bv = *(const float4*)(spB);
    {
        float* A0 = As[0]; float* B0 = Bs[0];
        A0[(k4 * 4 + 0) * GP + m_l] = av.x;
        A0[(k4 * 4 + 1) * GP + m_l] = av.y;
        A0[(k4 * 4 + 2) * GP + m_l] = av.z;
        A0[(k4 * 4 + 3) * GP + m_l] = av.w;
        *(float4*)(B0 + k_l * GP + n4 * 4) = bv;
    }
    __syncthreads();

    int buf = 0;
    for (int kc0 = 0; kc0 < KDIM; kc0 += 16) {
        const bool have_next = (kc0 + 16 < KDIM);
        if (have_next) {
            av = *(const float4*)(spA + kc0 + 16 + k4 * 4);
            bv = *(const float4*)(spB + (kc0 + 16) * NOUT);
        }

        const float* A = As[buf];
        const float* B = Bs[buf];
        float4 a0 = *(const float4*)(A + 0 * GP + ty * 4);
        float4 b0 = *(const float4*)(B + 0 * GP + tx * 4);
        #pragma unroll
        for (int k = 0; k < 16; k++) {
            float4 an, bn;
            if (k < 15) {
                an = *(const float4*)(A + (k + 1) * GP + ty * 4);
                bn = *(const float4*)(B + (k + 1) * GP + tx * 4);
            }
            acc[0][0] = fmaf(a0.x, b0.x, acc[0][0]); acc[0][1] = fmaf(a0.x, b0.y, acc[0][1]);
            acc[0][2] = fmaf(a0.x, b0.z, acc[0][2]); acc[0][3] = fmaf(a0.x, b0.w, acc[0][3]);
            acc[1][0] = fmaf(a0.y, b0.x, acc[1][0]); acc[1][1] = fmaf(a0.y, b0.y, acc[1][1]);
            acc[1][2] = fmaf(a0.y, b0.z, acc[1][2]); acc[1][3] = fmaf(a0.y, b0.w, acc[1][3]);
            acc[2][0] = fmaf(a0.z, b0.x, acc[2][0]); acc[2][1] = fmaf(a0.z, b0.y, acc[2][1]);
            acc[2][2] = fmaf(a0.z, b0.z, acc[2][2]); acc[2][3] = fmaf(a0.z, b0.w, acc[2][3]);
            acc[3][0] = fmaf(a0.w, b0.x, acc[3][0]); acc[3][1] = fmaf(a0.w, b0.y, acc[3][1]);
            acc[3][2] = fmaf(a0.w, b0.z, acc[3][2]); acc[3][3] = fmaf(a0.w, b0.w, acc[3][3]);
            if (k < 15) { a0 = an; b0 = bn; }
        }

        if (have_next) {
            float* An = As[buf ^ 1]; float* Bn = Bs[buf ^ 1];
            An[(k4 * 4 + 0) * GP + m_l] = av.x;
            An[(k4 * 4 + 1) * GP + m_l] = av.y;
            An[(k4 * 4 + 2) * GP + m_l] = av.z;
            An[(k4 * 4 + 3) * GP + m_l] = av.w;
            *(float4*)(Bn + k_l * GP + n4 * 4) = bv;
        }
        __syncthreads();
        buf ^= 1;
    }

    #pragma unroll
    for (int i = 0; i < 4; i++) {
        int m = m0 + ty * 4 + i;
        if (m < MROWS) {
            float4 v;
            if (EPI) {
                float4 bb = *(const float4*)(bias + n0 + tx * 4);
                v.x = elu1(acc[i][0] + bb.x);
                v.y = elu1(acc[i][1] + bb.y);
                v.z = elu1(acc[i][2] + bb.z);
                v.w = elu1(acc[i][3] + bb.w);
            } else {
                v = make_float4(acc[i][0], acc[i][1], acc[i][2], acc[i][3]);
            }
            *(float4*)(dst + m * NOUT + n0 + tx * 4) = v;
        }
    }
}

// ---------------------------------------------------------------------------
// comb: dst = elu(p0 + p1 + bias[ch]), once per element.
// CHQ = channel quads per row (NOUT/4), N4 = total float4 count.
// ---------------------------------------------------------------------------
template<int CHQ, int N4>
__global__ __launch_bounds__(256) void comb_kernel(
    const float* __restrict__ p0f, const float* __restrict__ p1f,
    const float* __restrict__ bias, float* __restrict__ dstf)
{
    int idx4 = blockIdx.x * 256 + threadIdx.x;
    if (idx4 >= N4) return;
    float4 a = ((const float4*)p0f)[idx4];
    float4 b = ((const float4*)p1f)[idx4];
    float4 bb = *(const float4*)(bias + (idx4 % CHQ) * 4);
    float4 v;
    v.x = elu1(a.x + b.x + bb.x);
    v.y = elu1(a.y + b.y + bb.y);
    v.z = elu1(a.z + b.z + bb.z);
    v.w = elu1(a.w + b.w + bb.w);
    ((float4*)dstf)[idx4] = v;
}

// ---------------------------------------------------------------------------
// rvq + head; z assembled on load from conv4 K-split partials (+bias, elu).
// blocks [0,120): rvq; [120,130): tail. 512 threads.
// rs padded to stride 6 u64 -> 2x LDS.128 + 1x LDS.64 per d.
// ---------------------------------------------------------------------------
#define RP 10
#define PH 5
#define RSP 6   // padded u64 stride per d (48B, 16B-aligned)
__global__ __launch_bounds__(512) void rvq_kernel(
    const float* __restrict__ cb,
    const float* __restrict__ b4c,
    const float* __restrict__ hb,
    float* __restrict__ out)
{
    __shared__ float zblk[RP * DM];                 // [p][d]; reused as head scratch
    __shared__ float2 zq2[DM * PH];                 // [dm][ph]
    __shared__ __align__(16) unsigned long long rs2u[CBD * RSP];  // [d][ph padded]
    __shared__ unsigned long long cand[RP * 16];
    __shared__ unsigned long long bestk[RP];

    const int tid = threadIdx.x;

    if (blockIdx.x >= 120) {
        // tail: 10 blocks x 512 = 4 batches x 1280
        int idx = (blockIdx.x - 120) * 512 + tid;
        int b = idx / 1280;
        int r = idx - b * 1280;
        int pos = b * TS + (TS - 1);
        if (r < 256) {
            int c = r >> 2, u = r & 3;
            out[OFF_S2 + (b * 64 + c) * 4 + u] = g_a1[pos * 704 + (7 + u) * 64 + c];
        } else if (r < 768) {
            int rr = r - 256;
            int c = rr >> 2, u = rr & 3;
            out[OFF_S3 + (b * 128 + c) * 4 + u] = g_a2[pos * 896 + (3 + u) * 128 + c];
        } else {
            int rr = r - 768;
            int c = rr >> 1, u = rr & 1;
            out[OFF_S4 + (b * 256 + c) * 2 + u] = g_a3[pos * 768 + (1 + u) * 256 + c];
        }
        return;
    }

    const int lane = tid & 31;
    const int wid = tid >> 5;
    const int b = blockIdx.x / 30;
    const int g = blockIdx.x % 30;

    // assemble z = elu(p0 + p1 + bias) on load
    for (int idx = tid; idx < RP * DM; idx += 512) {
        int p = idx >> 9, d = idx & 511;
        int gi = (b * TS + g * RP + p) * DM + d;
        zblk[idx] = elu1(g_zpart[0][gi] + g_zpart[1][gi] + b4c[d]);
    }
    __syncthreads();
    for (int idx = tid; idx < CBD * PH; idx += 512) {
        int d = idx / PH, ph = idx - d * PH;
        ((float2*)rs2u)[d * RSP + ph] =
            make_float2(zblk[(2 * ph) * DM + d], zblk[(2 * ph + 1) * DM + d]);
    }
    __syncthreads();

    for (int i = 0; i < NCB; i++) {
        const float* cbti = g_cbt + i * CBD * CBS;
        // thread handles codes (tid, tid+512)
        unsigned long long dot2[2][PH];
        #pragma unroll
        for (int q = 0; q < 2; q++)
            #pragma unroll
            for (int ph = 0; ph < PH; ph++) dot2[q][ph] = 0ull;

        for (int d = 0; d < CBD; d++) {
            float cv0 = cbti[d * CBS + tid];
            float cv1 = cbti[d * CBS + tid + 512];
            unsigned long long cp0 = pack2(cv0, cv0);
            unsigned long long cp1 = pack2(cv1, cv1);
            const unsigned long long* rp = rs2u + d * RSP;
            ulonglong2 rv01 = *(const ulonglong2*)rp;
            ulonglong2 rv23 = *(const ulonglong2*)(rp + 2);
            unsigned long long rv4 = rp[4];
            fma2(dot2[0][0], cp0, rv01.x); fma2(dot2[1][0], cp1, rv01.x);
            fma2(dot2[0][1], cp0, rv01.y); fma2(dot2[1][1], cp1, rv01.y);
            fma2(dot2[0][2], cp0, rv23.x); fma2(dot2[1][2], cp1, rv23.x);
            fma2(dot2[0][3], cp0, rv23.y); fma2(dot2[1][3], cp1, rv23.y);
            fma2(dot2[0][4], cp0, rv4);    fma2(dot2[1][4], cp1, rv4);
        }

        unsigned long long best[RP];
        #pragma unroll
        for (int p = 0; p < RP; p++) best[p] = 0ull;
        #pragma unroll
        for (int q = 0; q < 2; q++) {
            int code = tid + q * 512;
            float cn = g_cn[i * CBS + code];
            unsigned invc = ~(unsigned)code;
            #pragma unroll
            for (int ph = 0; ph < PH; ph++) {
                float sc0 = lo32(dot2[q][ph]) - cn;
                float sc1 = hi32(dot2[q][ph]) - cn;
                unsigned long long k0 = (((unsigned long long)fordu(sc0)) << 32) | invc;
                unsigned long long k1 = (((unsigned long long)fordu(sc1)) << 32) | invc;
                if (k0 > best[2 * ph])     best[2 * ph] = k0;
                if (k1 > best[2 * ph + 1]) best[2 * ph + 1] = k1;
            }
        }
        #pragma unroll
        for (int off = 16; off > 0; off >>= 1) {
            #pragma unroll
            for (int p = 0; p < RP; p++) {
                unsigned long long other = __shfl_down_sync(0xFFFFFFFFu, best[p], off);
                if (other > best[p]) best[p] = other;
            }
        }
        if (lane == 0) {
            #pragma unroll
            for (int p = 0; p < RP; p++) cand[p * 16 + wid] = best[p];
        }
        __syncthreads();
        if (tid < RP) {
            unsigned long long m = cand[tid * 16];
            #pragma unroll
            for (int w = 1; w < 16; w++) {
                unsigned long long v = cand[tid * 16 + w];
                if (v > m) m = v;
            }
            bestk[tid] = m;
            unsigned code = ~(unsigned)(m & 0xFFFFFFFFull);
            out[OFF_A + (b * NCB + i) * TS + g * RP + tid] = (float)code;
        }
        __syncthreads();
        for (int idx = tid; idx < CBD * PH; idx += 512) {
            int d = idx / PH, ph = idx - d * PH;
            int p0 = 2 * ph, p1 = p0 + 1;
            unsigned c0 = ~(unsigned)(bestk[p0] & 0xFFFFFFFFull);
            unsigned c1 = ~(unsigned)(bestk[p1] & 0xFFFFFFFFull);
            float q0 = cb[(i * CBS + c0) * CBD + d];
            float q1 = cb[(i * CBS + c1) * CBD + d];
            zq2[(i * 64 + d) * PH + ph] = make_float2(q0, q1);
            if (i < NCB - 1) {
                float2 r = ((float2*)rs2u)[d * RSP + ph];
                ((float2*)rs2u)[d * RSP + ph] = make_float2(
                    zblk[p0 * DM + (i + 1) * 64 + d] + r.x - q0,
                    zblk[p1 * DM + (i + 1) * 64 + d] + r.y - q1);
            }
        }
        __syncthreads();
    }

    // head split-D across the two 256-thread halves; combine via smem scratch
    {
        const int half = tid >> 8;
        const int ho = tid & 255;
        unsigned long long acc2[PH];
        #pragma unroll
        for (int ph = 0; ph < PH; ph++) acc2[ph] = 0ull;
        const unsigned long long* zqu = (const unsigned long long*)zq2;
        const int d0 = half * 256;
        for (int dm = d0; dm < d0 + 256; dm++) {
            float w = g_hwt[dm * 256 + ho];
            unsigned long long wp = pack2(w, w);
            #pragma unroll
            for (int ph = 0; ph < PH; ph++)
                fma2(acc2[ph], wp, zqu[dm * PH + ph]);
        }
        unsigned long long* ps = (unsigned long long*)zblk;
        if (half == 1) {
            #pragma unroll
            for (int ph = 0; ph < PH; ph++) ps[ho * PH + ph] = acc2[ph];
        }
        __syncthreads();
        if (half == 0) {
            int h = ho >> 6, o = ho & 63;
            float bb = hb[ho];
            #pragma unroll
            for (int ph = 0; ph < PH; ph++) {
                unsigned long long other = ps[ho * PH + ph];
                int p0 = 2 * ph, p1 = p0 + 1;
                float v0 = lo32(acc2[ph]) + lo32(other) + bb;
                float v1 = hi32(acc2[ph]) + hi32(other) + bb;
                out[OFF_BL + ((b * 4 + h) * TS + g * RP + p0) * 64 + o] = v0;
                out[OFF_BL + ((b * 4 + h) * TS + g * RP + p1) * 64 + o] = v1;
            }
        }
    }
}

// ---------------------------------------------------------------------------
extern "C" void kernel_launch(void* const* d_in, const int* in_sizes, int n_in,
                              void* d_out, int out_size)
{
    const float* audio = (const float*)d_in[0];
    const float* w1 = (const float*)d_in[1];
    const float* b1 = (const float*)d_in[2];
    const float* w2 = (const float*)d_in[3];
    const float* b2 = (const float*)d_in[4];
    const float* w3 = (const float*)d_in[5];
    const float* b3 = (const float*)d_in[6];
    const float* w4 = (const float*)d_in[7];
    const float* b4 = (const float*)d_in[8];
    const float* cb = (const float*)d_in[9];
    const float* hw = (const float*)d_in[10];
    const float* hb = (const float*)d_in[11];
    float* out = (float*)d_out;

    prep_conv1_kernel<<<1630, 256>>>(w2, w3, w4, hw, cb, audio, w1, b1, out);

    float* g_a1p;   cudaGetSymbolAddress((void**)&g_a1p, g_a1);
    float* g_a2pp;  cudaGetSymbolAddress((void**)&g_a2pp, g_a2part);
    float* g_a2p;   cudaGetSymbolAddress((void**)&g_a2p, g_a2);
    float* g_a3pp;  cudaGetSymbolAddress((void**)&g_a3pp, g_a3part);
    float* g_a3p;   cudaGetSymbolAddress((void**)&g_a3p, g_a3);
    float* g_zpp;   cudaGetSymbolAddress((void**)&g_zpp, g_zpart);
    float* g_w2tp;  cudaGetSymbolAddress((void**)&g_w2tp, g_w2t);
    float* g_w3tp;  cudaGetSymbolAddress((void**)&g_w3tp, g_w3t);
    float* g_w4tp;  cudaGetSymbolAddress((void**)&g_w4tp, g_w4t);

    // conv2: K=320 split 2x160, raw partials; grid (132, 2*2)
    gemm_conv<160, 128, 8400, 7, 704, 64, 0, 2><<<dim3(132, 4), 256>>>(g_a1p, g_w2tp, b2, g_a2pp);
    // combine conv2 partials -> g_a2 (once per element); N4 = 8400*128/4 = 268800
    comb_kernel<32, 268800><<<1050, 256>>>(g_a2pp, g_a2pp + N_A2, b2, g_a2p);
    // conv3: K=640 split 2x320, raw partials; grid (57, 2*4)
    gemm_conv<320, 256, 3600, 3, 896, 128, 0, 2><<<dim3(57, 8), 256>>>(g_a2p, g_w3tp, b3, g_a3pp);
    // combine conv3 partials -> g_a3; N4 = 3600*256/4 = 230400
    comb_kernel<64, 230400><<<900, 256>>>(g_a3pp, g_a3pp + N_A3, b3, g_a3p);
    // conv4: K=768 split 2x384, raw partials; combined in rvq's z load
    gemm_conv<384, 512, 1200, 1, 768, 0, 0, 2><<<dim3(19, 32 / 2), 256>>>(g_a3p, g_w4tp, b4, g_zpp);

    rvq_kernel<<<130, 512>>>(cb, b4, hb, out);
}

// round 15
// speedup vs baseline: 1.0969x; 1.0969x over previous
#include <cuda_runtime.h>
#include <math.h>

#define NB 4
#define T 72000
#define TS 300
#define NCB 8
#define CBS 1024
#define CBD 64
#define DM 512

// out offsets (floats): a_tokens, b_logits, s1, s2, s3, s4
#define OFF_A  0
#define OFF_BL 9600
#define OFF_S1 316800
#define OFF_S2 316824
#define OFF_S3 317848
#define OFF_S4 319896

#define NPOS (NB * TS)   // 1200
#define N_A3 (NPOS * 3 * 256)

__device__ float g_cn[NCB * CBS];         // 0.5*|c|^2
__device__ float g_w2t[320 * 128];        // [(kk*64+i)][o]
__device__ float g_w3t[640 * 256];        // [(kk*128+i)][o]
__device__ float g_w4t[768 * 512];        // [(kk*256+i)][o]
__device__ float g_hwt[DM * 256];         // [d][h*64+o]
__device__ float g_cbt[NCB * CBD * CBS];  // [i][d][code]
__device__ float g_a1[NPOS * 11 * 64];    // elu(conv1) [pos][off 0..10][ch]
__device__ float g_a2[NPOS * 7 * 128];    // elu(conv2) [pos][off 0..6][ch]
__device__ float g_a3part[2][N_A3];       // conv3 K-split partials (raw)
__device__ float g_a3[N_A3];              // elu(conv3) combined
__device__ float g_zpart[2][NPOS * DM];   // conv4 K-split partials (raw)

__device__ __forceinline__ float elu1(float x) { return x > 0.f ? x : expm1f(x); }

__device__ __forceinline__ unsigned fordu(float f) {
    unsigned u = __float_as_uint(f);
    return u ^ (unsigned)(((int)u >> 31) | 0x80000000);
}

// packed f32x2 helpers (rvq dot phase)
__device__ __forceinline__ unsigned long long pack2(float lo, float hi) {
    unsigned long long r;
    asm("mov.b64 %0, {%1, %2};" : "=l"(r) : "f"(lo), "f"(hi));
    return r;
}
__device__ __forceinline__ void fma2(unsigned long long& d,
                                     unsigned long long a, unsigned long long b) {
    asm("fma.rn.f32x2 %0, %1, %2, %0;" : "+l"(d) : "l"(a), "l"(b));
}
__device__ __forceinline__ float lo32(unsigned long long v) {
    return __uint_as_float((unsigned)v);
}
__device__ __forceinline__ float hi32(unsigned long long v) {
    return __uint_as_float((unsigned)(v >> 32));
}

// ---------------------------------------------------------------------------
// prep + conv1 merged. blocks [0,1224): transposes, [1224,1480): code norms,
// [1480,1630): conv1 (150 blocks x 8 positions).
// ---------------------------------------------------------------------------
__global__ __launch_bounds__(256) void prep_conv1_kernel(
    const float* __restrict__ w2, const float* __restrict__ w3,
    const float* __restrict__ w4, const float* __restrict__ hw,
    const float* __restrict__ cb,
    const float* __restrict__ audio,
    const float* __restrict__ w1c, const float* __restrict__ b1c,
    float* __restrict__ out)
{
    __shared__ float ts[32 * 33];
    __shared__ float aud[8 * 17];
    __shared__ float w1s[64 * 7];
    const int tid = threadIdx.x;
    int bid = blockIdx.x;

    if (bid < 1224) {
        const float* src; float* dst;
        int r0, c0, SP, NO, cdiv, cmul, cin, dbase = 0;
        if (bid < 40) {                // w2: src 128x320 -> dst[(kk*64+i)][o]
            src = w2; dst = g_w2t; SP = 320; NO = 128; cdiv = 5; cmul = 64; cin = 1;
            r0 = (bid & 3) * 32; c0 = (bid >> 2) * 32;
        } else if (bid < 200) {        // w3: 256x640
            bid -= 40;
            src = w3; dst = g_w3t; SP = 640; NO = 256; cdiv = 5; cmul = 128; cin = 1;
            r0 = (bid & 7) * 32; c0 = (bid >> 3) * 32;
        } else if (bid < 584) {        // w4: 512x768
            bid -= 200;
            src = w4; dst = g_w4t; SP = 768; NO = 512; cdiv = 3; cmul = 256; cin = 1;
            r0 = (bid & 15) * 32; c0 = (bid >> 4) * 32;
        } else if (bid < 712) {        // hw: 256x512 plain transpose
            bid -= 584;
            src = hw; dst = g_hwt; SP = 512; NO = 256; cdiv = 1; cmul = 1; cin = 0;
            r0 = (bid & 7) * 32; c0 = (bid >> 3) * 32;
        } else {                       // cb: per-codebook 1024x64 plain transpose
            bid -= 712;
            int i = bid >> 6; int t = bid & 63;
            src = cb + i * 65536; dst = g_cbt; dbase = i * 65536;
            SP = 64; NO = 1024; cdiv = 1; cmul = 1; cin = 0;
            r0 = (t >> 1) * 32; c0 = (t & 1) * 32;
        }
        for (int l = tid; l < 1024; l += 256) {
            int r = l >> 5, c = l & 31;
            ts[r * 33 + c] = src[(r0 + r) * SP + c0 + c];
        }
        __syncthreads();
        for (int l = tid; l < 1024; l += 256) {
            int r = l >> 5, c = l & 31;
            int colidx = c0 + r;
            int drow;
            if (cin) drow = (colidx % cdiv) * cmul + colidx / cdiv;
            else     drow = colidx;
            dst[dbase + drow * NO + r0 + c] = ts[c * 33 + r];
        }
    } else if (bid < 1480) {
        bid -= 1224;
        const int wid = tid >> 5, lane = tid & 31;
        int code0 = bid * 32 + wid * 4;
        #pragma unroll
        for (int cc = 0; cc < 4; cc++) {
            const float* p = cb + (code0 + cc) * CBD;
            float v1 = p[lane], v2 = p[lane + 32];
            float s = fmaf(v1, v1, v2 * v2);
            #pragma unroll
            for (int off = 16; off > 0; off >>= 1)
                s += __shfl_down_sync(0xFFFFFFFFu, s, off);
            if (lane == 0) g_cn[code0 + cc] = 0.5f * s;
        }
    } else {
        // conv1: 8 positions per block
        bid -= 1480;
        const int pos0 = bid * 8;
        for (int idx = tid; idx < 64 * 7; idx += 256) w1s[idx] = w1c[idx];
        for (int idx = tid; idx < 8 * 17; idx += 256) {
            int p = idx / 17, u = idx - p * 17;
            int pos = pos0 + p;
            int b = pos / TS, t = pos - b * TS;
            aud[idx] = audio[b * T + t * 240 + 223 + u];
        }
        __syncthreads();
        for (int idx = tid; idx < 8 * 11 * 64; idx += 256) {
            int ch = idx & 63;
            int r = idx >> 6;
            int j = r % 11, p = r / 11;
            float acc = b1c[ch];
            #pragma unroll
            for (int k = 0; k < 7; k++) acc = fmaf(w1s[ch * 7 + k], aud[p * 17 + j + k], acc);
            g_a1[(pos0 + p) * 704 + j * 64 + ch] = elu1(acc);
        }
        if (bid == 0 && tid < 24) {
            int b = tid / 6, u = tid % 6;
            out[OFF_S1 + tid] = audio[b * T + (T - 6) + u];
        }
    }
}

// ---------------------------------------------------------------------------
// smem-smem GEMM conv: BM=64, BN=64, BK=16, 256 thr, 4x4 reg tile,
// double-buffered smem + register-pipelined LDS.
// EPI=1: dst = elu(acc + bias). EPI=0: dst = raw acc (partial).
// NSPL: K-splits on blockIdx.y (y = spl*(NOUT/64) + ntile).
// ---------------------------------------------------------------------------
#define GP 68
template<int KDIM, int NOUT, int MROWS, int JDIV, int JMUL, int CH, int EPI, int NSPL>
__global__ __launch_bounds__(256) void gemm_conv(
    const float* __restrict__ src, const float* __restrict__ wt,
    const float* __restrict__ bias, float* __restrict__ dst)
{
    __shared__ float As[2][16 * GP];
    __shared__ float Bs[2][16 * GP];

    const int tid = threadIdx.x;
    const int tx = tid & 15;
    const int ty = tid >> 4;
    const int m0 = blockIdx.x * 64;
    int yb = blockIdx.y;
    if (NSPL > 1) {
        int spl = yb / (NOUT / 64);
        yb -= spl * (NOUT / 64);
        src += spl * KDIM;            // additive k-origin (k contiguous per row window)
        wt  += spl * KDIM * NOUT;
        dst += spl * MROWS * NOUT;
    }
    const int n0 = yb * 64;

    const int m_l = tid & 63;
    const int k4 = tid >> 6;
    int mrow = m0 + m_l; if (mrow >= MROWS) mrow = MROWS - 1;   // clamp (stores guarded)
    const float* spA = src + (mrow / JDIV) * JMUL + (mrow % JDIV) * CH;

    const int k_l = tid >> 4;
    const int n4 = tid & 15;
    const float* spB = wt + k_l * NOUT + n0 + n4 * 4;

    float acc[4][4];
    #pragma unroll
    for (int i = 0; i < 4; i++)
        #pragma unroll
        for (int j = 0; j < 4; j++) acc[i][j] = 0.f;

    float4 av = *(const float4*)(spA + k4 * 4);
    float4 bv = *(const float4*)(spB);
    {
        float* A0 = As[0]; float* B0 = Bs[0];
        A0[(k4 * 4 + 0) * GP + m_l] = av.x;
        A0[(k4 * 4 + 1) * GP + m_l] = av.y;
        A0[(k4 * 4 + 2) * GP + m_l] = av.z;
        A0[(k4 * 4 + 3) * GP + m_l] = av.w;
        *(float4*)(B0 + k_l * GP + n4 * 4) = bv;
    }
    __syncthreads();

    int buf = 0;
    for (int kc0 = 0; kc0 < KDIM; kc0 += 16) {
        const bool have_next = (kc0 + 16 < KDIM);
        if (have_next) {
            av = *(const float4*)(spA + kc0 + 16 + k4 * 4);
            bv = *(const float4*)(spB + (kc0 + 16) * NOUT);
        }

        const float* A = As[buf];
        const float* B = Bs[buf];
        float4 a0 = *(const float4*)(A + 0 * GP + ty * 4);
        float4 b0 = *(const float4*)(B + 0 * GP + tx * 4);
        #pragma unroll
        for (int k = 0; k < 16; k++) {
            float4 an, bn;
            if (k < 15) {
                an = *(const float4*)(A + (k + 1) * GP + ty * 4);
                bn = *(const float4*)(B + (k + 1) * GP + tx * 4);
            }
            acc[0][0] = fmaf(a0.x, b0.x, acc[0][0]); acc[0][1] = fmaf(a0.x, b0.y, acc[0][1]);
            acc[0][2] = fmaf(a0.x, b0.z, acc[0][2]); acc[0][3] = fmaf(a0.x, b0.w, acc[0][3]);
            acc[1][0] = fmaf(a0.y, b0.x, acc[1][0]); acc[1][1] = fmaf(a0.y, b0.y, acc[1][1]);
            acc[1][2] = fmaf(a0.y, b0.z, acc[1][2]); acc[1][3] = fmaf(a0.y, b0.w, acc[1][3]);
            acc[2][0] = fmaf(a0.z, b0.x, acc[2][0]); acc[2][1] = fmaf(a0.z, b0.y, acc[2][1]);
            acc[2][2] = fmaf(a0.z, b0.z, acc[2][2]); acc[2][3] = fmaf(a0.z, b0.w, acc[2][3]);
            acc[3][0] = fmaf(a0.w, b0.x, acc[3][0]); acc[3][1] = fmaf(a0.w, b0.y, acc[3][1]);
            acc[3][2] = fmaf(a0.w, b0.z, acc[3][2]); acc[3][3] = fmaf(a0.w, b0.w, acc[3][3]);
            if (k < 15) { a0 = an; b0 = bn; }
        }

        if (have_next) {
            float* An = As[buf ^ 1]; float* Bn = Bs[buf ^ 1];
            An[(k4 * 4 + 0) * GP + m_l] = av.x;
            An[(k4 * 4 + 1) * GP + m_l] = av.y;
            An[(k4 * 4 + 2) * GP + m_l] = av.z;
            An[(k4 * 4 + 3) * GP + m_l] = av.w;
            *(float4*)(Bn + k_l * GP + n4 * 4) = bv;
        }
        __syncthreads();
        buf ^= 1;
    }

    #pragma unroll
    for (int i = 0; i < 4; i++) {
        int m = m0 + ty * 4 + i;
        if (m < MROWS) {
            float4 v;
            if (EPI) {
                float4 bb = *(const float4*)(bias + n0 + tx * 4);
                v.x = elu1(acc[i][0] + bb.x);
                v.y = elu1(acc[i][1] + bb.y);
                v.z = elu1(acc[i][2] + bb.z);
                v.w = elu1(acc[i][3] + bb.w);
            } else {
                v = make_float4(acc[i][0], acc[i][1], acc[i][2], acc[i][3]);
            }
            *(float4*)(dst + m * NOUT + n0 + tx * 4) = v;
        }
    }
}

// ---------------------------------------------------------------------------
// comb3: g_a3 = elu(p0 + p1 + b3[ch]), once per element. 900 blocks x 256.
// ---------------------------------------------------------------------------
__global__ __launch_bounds__(256) void comb3_kernel(const float* __restrict__ b3) {
    int idx4 = blockIdx.x * 256 + threadIdx.x;        // 230400 float4s
    float4 a = ((const float4*)g_a3part[0])[idx4];
    float4 b = ((const float4*)g_a3part[1])[idx4];
    float4 bb = *(const float4*)(b3 + ((idx4 & 63) << 2));
    float4 v;
    v.x = elu1(a.x + b.x + bb.x);
    v.y = elu1(a.y + b.y + bb.y);
    v.z = elu1(a.z + b.z + bb.z);
    v.w = elu1(a.w + b.w + bb.w);
    ((float4*)g_a3)[idx4] = v;
}

// ---------------------------------------------------------------------------
// rvq + head: 8 positions per block, 150 rvq blocks (full wave) + 10 tail.
// 512 threads. Per-position batch indexing (300 not divisible by 8).
// rs stride 4 u64 = 32B -> 2x LDS.128 broadcast per d.
// ---------------------------------------------------------------------------
#define RP 8
#define PH 4
__global__ __launch_bounds__(512) void rvq_kernel(
    const float* __restrict__ cb,
    const float* __restrict__ b4c,
    const float* __restrict__ hb,
    float* __restrict__ out)
{
    __shared__ float zblk[RP * DM];                 // [p][d]; reused as head scratch
    __shared__ float2 zq2[DM * PH];                 // [dm][ph]
    __shared__ __align__(16) unsigned long long rs2u[CBD * PH];   // [d][ph]
    __shared__ unsigned long long cand[RP * 16];
    __shared__ unsigned long long bestk[RP];

    const int tid = threadIdx.x;

    if (blockIdx.x >= 150) {
        // tail: 10 blocks x 512 = 4 batches x 1280
        int idx = (blockIdx.x - 150) * 512 + tid;
        int b = idx / 1280;
        int r = idx - b * 1280;
        int pos = b * TS + (TS - 1);
        if (r < 256) {
            int c = r >> 2, u = r & 3;
            out[OFF_S2 + (b * 64 + c) * 4 + u] = g_a1[pos * 704 + (7 + u) * 64 + c];
        } else if (r < 768) {
            int rr = r - 256;
            int c = rr >> 2, u = rr & 3;
            out[OFF_S3 + (b * 128 + c) * 4 + u] = g_a2[pos * 896 + (3 + u) * 128 + c];
        } else {
            int rr = r - 768;
            int c = rr >> 1, u = rr & 1;
            out[OFF_S4 + (b * 256 + c) * 2 + u] = g_a3[pos * 768 + (1 + u) * 256 + c];
        }
        return;
    }

    const int lane = tid & 31;
    const int wid = tid >> 5;
    const int pos0 = blockIdx.x * RP;    // global position base

    // assemble z = elu(p0 + p1 + bias) on load
    for (int idx = tid; idx < RP * DM; idx += 512) {
        int p = idx >> 9, d = idx & 511;
        int gi = (pos0 + p) * DM + d;
        zblk[idx] = elu1(g_zpart[0][gi] + g_zpart[1][gi] + b4c[d]);
    }
    __syncthreads();
    for (int idx = tid; idx < CBD * PH; idx += 512) {
        int d = idx >> 2, ph = idx & 3;
        ((float2*)rs2u)[d * PH + ph] =
            make_float2(zblk[(2 * ph) * DM + d], zblk[(2 * ph + 1) * DM + d]);
    }
    __syncthreads();

    for (int i = 0; i < NCB; i++) {
        const float* cbti = g_cbt + i * CBD * CBS;
        // thread handles codes (tid, tid+512)
        unsigned long long dot2[2][PH];
        #pragma unroll
        for (int q = 0; q < 2; q++)
            #pragma unroll
            for (int ph = 0; ph < PH; ph++) dot2[q][ph] = 0ull;

        for (int d = 0; d < CBD; d++) {
            float cv0 = cbti[d * CBS + tid];
            float cv1 = cbti[d * CBS + tid + 512];
            unsigned long long cp0 = pack2(cv0, cv0);
            unsigned long long cp1 = pack2(cv1, cv1);
            const unsigned long long* rp = rs2u + d * PH;
            ulonglong2 rv01 = *(const ulonglong2*)rp;
            ulonglong2 rv23 = *(const ulonglong2*)(rp + 2);
            fma2(dot2[0][0], cp0, rv01.x); fma2(dot2[1][0], cp1, rv01.x);
            fma2(dot2[0][1], cp0, rv01.y); fma2(dot2[1][1], cp1, rv01.y);
            fma2(dot2[0][2], cp0, rv23.x); fma2(dot2[1][2], cp1, rv23.x);
            fma2(dot2[0][3], cp0, rv23.y); fma2(dot2[1][3], cp1, rv23.y);
        }

        unsigned long long best[RP];
        #pragma unroll
        for (int p = 0; p < RP; p++) best[p] = 0ull;
        #pragma unroll
        for (int q = 0; q < 2; q++) {
            int code = tid + q * 512;
            float cn = g_cn[i * CBS + code];
            unsigned invc = ~(unsigned)code;
            #pragma unroll
            for (int ph = 0; ph < PH; ph++) {
                float sc0 = lo32(dot2[q][ph]) - cn;
                float sc1 = hi32(dot2[q][ph]) - cn;
                unsigned long long k0 = (((unsigned long long)fordu(sc0)) << 32) | invc;
                unsigned long long k1 = (((unsigned long long)fordu(sc1)) << 32) | invc;
                if (k0 > best[2 * ph])     best[2 * ph] = k0;
                if (k1 > best[2 * ph + 1]) best[2 * ph + 1] = k1;
            }
        }
        #pragma unroll
        for (int off = 16; off > 0; off >>= 1) {
            #pragma unroll
            for (int p = 0; p < RP; p++) {
                unsigned long long other = __shfl_down_sync(0xFFFFFFFFu, best[p], off);
                if (other > best[p]) best[p] = other;
            }
        }
        if (lane == 0) {
            #pragma unroll
            for (int p = 0; p < RP; p++) cand[p * 16 + wid] = best[p];
        }
        __syncthreads();
        if (tid < RP) {
            unsigned long long m = cand[tid * 16];
            #pragma unroll
            for (int w = 1; w < 16; w++) {
                unsigned long long v = cand[tid * 16 + w];
                if (v > m) m = v;
            }
            bestk[tid] = m;
            unsigned code = ~(unsigned)(m & 0xFFFFFFFFull);
            int pos = pos0 + tid;
            int b = pos / TS, t = pos - b * TS;
            out[OFF_A + (b * NCB + i) * TS + t] = (float)code;
        }
        __syncthreads();
        for (int idx = tid; idx < CBD * PH; idx += 512) {
            int d = idx >> 2, ph = idx & 3;
            int p0 = 2 * ph, p1 = p0 + 1;
            unsigned c0 = ~(unsigned)(bestk[p0] & 0xFFFFFFFFull);
            unsigned c1 = ~(unsigned)(bestk[p1] & 0xFFFFFFFFull);
            float q0 = cb[(i * CBS + c0) * CBD + d];
            float q1 = cb[(i * CBS + c1) * CBD + d];
            zq2[(i * 64 + d) * PH + ph] = make_float2(q0, q1);
            if (i < NCB - 1) {
                float2 r = ((float2*)rs2u)[d * PH + ph];
                ((float2*)rs2u)[d * PH + ph] = make_float2(
                    zblk[p0 * DM + (i + 1) * 64 + d] + r.x - q0,
                    zblk[p1 * DM + (i + 1) * 64 + d] + r.y - q1);
            }
        }
        __syncthreads();
    }

    // head split-D across the two 256-thread halves; combine via smem scratch
    {
        const int half = tid >> 8;
        const int ho = tid & 255;
        unsigned long long acc2[PH];
        #pragma unroll
        for (int ph = 0; ph < PH; ph++) acc2[ph] = 0ull;
        const unsigned long long* zqu = (const unsigned long long*)zq2;
        const int d0 = half * 256;
        for (int dm = d0; dm < d0 + 256; dm++) {
            float w = g_hwt[dm * 256 + ho];
            unsigned long long wp = pack2(w, w);
            #pragma unroll
            for (int ph = 0; ph < PH; ph++)
                fma2(acc2[ph], wp, zqu[dm * PH + ph]);
        }
        unsigned long long* ps = (unsigned long long*)zblk;
        if (half == 1) {
            #pragma unroll
            for (int ph = 0; ph < PH; ph++) ps[ho * PH + ph] = acc2[ph];
        }
        __syncthreads();
        if (half == 0) {
            int h = ho >> 6, o = ho & 63;
            float bb = hb[ho];
            #pragma unroll
            for (int ph = 0; ph < PH; ph++) {
                unsigned long long other = ps[ho * PH + ph];
                int pos_0 = pos0 + 2 * ph;
                int pos_1 = pos_0 + 1;
                int b0i = pos_0 / TS, t0i = pos_0 - b0i * TS;
                int b1i = pos_1 / TS, t1i = pos_1 - b1i * TS;
                float v0 = lo32(acc2[ph]) + lo32(other) + bb;
                float v1 = hi32(acc2[ph]) + hi32(other) + bb;
                out[OFF_BL + ((b0i * 4 + h) * TS + t0i) * 64 + o] = v0;
                out[OFF_BL + ((b1i * 4 + h) * TS + t1i) * 64 + o] = v1;
            }
        }
    }
}

// ---------------------------------------------------------------------------
extern "C" void kernel_launch(void* const* d_in, const int* in_sizes, int n_in,
                              void* d_out, int out_size)
{
    const float* audio = (const float*)d_in[0];
    const float* w1 = (const float*)d_in[1];
    const float* b1 = (const float*)d_in[2];
    const float* w2 = (const float*)d_in[3];
    const float* b2 = (const float*)d_in[4];
    const float* w3 = (const float*)d_in[5];
    const float* b3 = (const float*)d_in[6];
    const float* w4 = (const float*)d_in[7];
    const float* b4 = (const float*)d_in[8];
    const float* cb = (const float*)d_in[9];
    const float* hw = (const float*)d_in[10];
    const float* hb = (const float*)d_in[11];
    float* out = (float*)d_out;

    prep_conv1_kernel<<<1630, 256>>>(w2, w3, w4, hw, cb, audio, w1, b1, out);

    float* g_a1p;   cudaGetSymbolAddress((void**)&g_a1p, g_a1);
    float* g_a2p;   cudaGetSymbolAddress((void**)&g_a2p, g_a2);
    float* g_a3pp;  cudaGetSymbolAddress((void**)&g_a3pp, g_a3part);
    float* g_a3p;   cudaGetSymbolAddress((void**)&g_a3p, g_a3);
    float* g_zpp;   cudaGetSymbolAddress((void**)&g_zpp, g_zpart);
    float* g_w2tp;  cudaGetSymbolAddress((void**)&g_w2tp, g_w2t);
    float* g_w3tp;  cudaGetSymbolAddress((void**)&g_w3tp, g_w3t);
    float* g_w4tp;  cudaGetSymbolAddress((void**)&g_w4tp, g_w4t);

    // conv2: full K, fused elu epilogue
    gemm_conv<320, 128, 8400, 7, 704, 64, 1, 1><<<dim3(132, 2), 256>>>(g_a1p, g_w2tp, b2, g_a2p);
    // conv3: K=640 split 2x320, raw partials; grid (57, 2*4)
    gemm_conv<320, 256, 3600, 3, 896, 128, 0, 2><<<dim3(57, 8), 256>>>(g_a2p, g_w3tp, b3, g_a3pp);
    // combine partials -> g_a3 (once per element)
    comb3_kernel<<<900, 256>>>(b3);
    // conv4: K=768 split 2x384, raw partials; combined in rvq's z load
    gemm_conv<384, 512, 1200, 1, 768, 0, 0, 2><<<dim3(19, 16), 256>>>(g_a3p, g_w4tp, b4, g_zpp);

    rvq_kernel<<<160, 512>>>(cb, b4, hb, out);
}